// round 15
// baseline (speedup 1.0000x reference)
#include <cuda_runtime.h>
#include <cuda_bf16.h>
#include <cstdint>

// ---------------- constants ----------------
#define NPATCH 1024          // 64 tiles * B=16
#define NG     8192          // NPATCH * G

// ---------------- scratch ----------------
__device__ float g_xp[NPATCH * 256 * 64];    // normalized, patchified x  [n][c][i]
__device__ float g_ao[NPATCH * 64 * 512];    // attention output (tf32-rounded) [n][i][r]
__device__ float g_wo32[256 * 512];          // wo, tf32-rounded [c][r]
__device__ float g_wqT[8 * 32 * 64];         // wq transposed [g][c][o]
__device__ float g_wkT[8 * 32 * 64];         // wk transposed [g][c][o]
__device__ float g_wvT[8 * 32 * 64];         // wv transposed [g][c][o]
__device__ __nv_bfloat16 g_w2b[64 * 72];     // cpb w2 transposed, bf16, stride 72

// ---------------- mma helpers ----------------
static __device__ __forceinline__ void mma_bf16(float* d, const unsigned* a,
                                                unsigned b0, unsigned b1) {
    asm volatile("mma.sync.aligned.m16n8k16.row.col.f32.bf16.bf16.f32 "
        "{%0,%1,%2,%3},{%4,%5,%6,%7},{%8,%9},{%0,%1,%2,%3};"
        : "+f"(d[0]), "+f"(d[1]), "+f"(d[2]), "+f"(d[3])
        : "r"(a[0]), "r"(a[1]), "r"(a[2]), "r"(a[3]), "r"(b0), "r"(b1));
}
static __device__ __forceinline__ void mma_tf32(float* d, const unsigned* a,
                                                unsigned b0, unsigned b1) {
    asm volatile("mma.sync.aligned.m16n8k8.row.col.f32.tf32.tf32.f32 "
        "{%0,%1,%2,%3},{%4,%5,%6,%7},{%8,%9},{%0,%1,%2,%3};"
        : "+f"(d[0]), "+f"(d[1]), "+f"(d[2]), "+f"(d[3])
        : "r"(a[0]), "r"(a[1]), "r"(a[2]), "r"(a[3]), "r"(b0), "r"(b1));
}
static __device__ __forceinline__ float cvt_tf32(float x) {
    float r; asm("cvt.rna.tf32.f32 %0, %1;" : "=f"(r) : "f"(x)); return r;
}
static __device__ __forceinline__ uint32_t smem_u32(const void* p) {
    uint32_t a;
    asm("{ .reg .u64 t; cvta.to.shared.u64 t, %1; cvt.u32.u64 %0, t; }" : "=r"(a) : "l"(p));
    return a;
}
static __device__ __forceinline__ void cpa16(uint32_t dst, const void* src) {
    asm volatile("cp.async.ca.shared.global [%0], [%1], 16;" :: "r"(dst), "l"(src) : "memory");
}
#define CPA_COMMIT() asm volatile("cp.async.commit_group;" ::: "memory")
#define CPA_WAIT1()  asm volatile("cp.async.wait_group 1;" ::: "memory")
#define CPA_WAIT0()  asm volatile("cp.async.wait_group 0;" ::: "memory")

// ---------------- K0: all weight preprocessing in one kernel ----------------
__global__ void k0_prep(const float* __restrict__ wo, const float* __restrict__ cw2g,
                        const float* __restrict__ wq,
                        const float* __restrict__ wk, const float* __restrict__ wv) {
    int idx = blockIdx.x * 256 + threadIdx.x;
    if (idx < 256 * 512) g_wo32[idx] = cvt_tf32(wo[idx]);
    if (idx < 64 * 72) {
        int o = idx / 72, k = idx % 72;
        g_w2b[idx] = (k < 64) ? __float2bfloat16(cw2g[k * 64 + o]) : __float2bfloat16(0.f);
    }
    if (idx < 8 * 64 * 32) {
        int g = idx >> 11, rem = idx & 2047, o = rem >> 5, c = rem & 31;
        int d = g * 2048 + c * 64 + o;
        g_wqT[d] = wq[idx];
        g_wkT[d] = wk[idx];
        g_wvT[d] = wv[idx];
    }
}

// ---------------- K1: LayerNorm over C + patchify ----------------
__global__ void __launch_bounds__(256) k1_ln_patch(const float* __restrict__ x,
                                                   const float* __restrict__ ln_g,
                                                   const float* __restrict__ ln_b) {
    __shared__ float sb[256 * 32];
    __shared__ float rs[8 * 32], rq2[8 * 32];
    __shared__ float smu[32], srd[32];

    int bid  = blockIdx.x;
    int b    = bid >> 7;
    int h    = (bid >> 1) & 63;
    int half = bid & 1;
    int w0   = half * 32;
    int tid  = threadIdx.x;
    int wl   = tid & 31;
    int cs   = tid >> 5;

    float sum = 0.f, sq = 0.f;
    const float* xb = x + (((long)b * 256 + cs * 32) * 64 + h) * 64 + w0 + wl;
    #pragma unroll 8
    for (int m = 0; m < 32; m++) {
        float v = xb[m * 4096];
        sb[(cs * 32 + m) * 32 + wl] = v;
        sum += v; sq += v * v;
    }
    rs[cs * 32 + wl] = sum;
    rq2[cs * 32 + wl] = sq;
    __syncthreads();
    if (tid < 32) {
        float S = 0.f, Q = 0.f;
        #pragma unroll
        for (int s = 0; s < 8; s++) { S += rs[s * 32 + tid]; Q += rq2[s * 32 + tid]; }
        float mu  = S * (1.f / 256.f);
        float var = Q * (1.f / 256.f) - mu * mu;
        smu[tid] = mu;
        srd[tid] = rsqrtf(var + 1e-6f);
    }
    __syncthreads();
    float mu = smu[wl], rd = srd[wl];
    int w  = w0 + wl;
    int it = h >> 3, p = h & 7, jt = w >> 3, q = w & 7;
    int n  = it * 128 + jt * 16 + b;
    float* dst = g_xp + (long)n * 256 * 64 + p * 8 + q;
    #pragma unroll 8
    for (int m = 0; m < 32; m++) {
        int c = cs * 32 + m;
        float v = (sb[c * 32 + wl] - mu) * rd * __ldg(ln_g + c) + __ldg(ln_b + c);
        dst[c * 64] = v;
    }
}

// ---------------- K2: per-(n,g) deformable attention ----------------
#define SM_XG   0        // 2048
#define SM_W    2048     // 4096 (wkT|wvT [c][o], loaded in P2)
#define SM_QT   6144     // 64*68 = 4352, ends 10496
#define SM_W2B  9216     // overlay (P6b+): 64 rows x 36 floats, ends 11520
#define SM_GB   11520    // 256
#define SM_KV   11776    // 128
#define SM_KKT  11904    // 4*68 = 272
#define SM_VVT  12176    // 4*68 = 272
#define SM_LG   12448    // 256
#define SM_SP   12704    // 16
#define SM_C1   12720    // 128
#define SM_B1   12848    // 64
#define SM_B2   12912    // 64
#define SM_C3   12976    // 64
#define SM_B3   13040    // 4
#define K2_SMEM_BYTES (13044 * 4)

__global__ void __launch_bounds__(256, 4) k2_attn(
    const float* __restrict__ ow1, const float* __restrict__ ob1, const float* __restrict__ ow2,
    const float* __restrict__ cw1g, const float* __restrict__ cb1g,
    const float* __restrict__ cb2g,
    const float* __restrict__ cw3g, const float* __restrict__ cb3g) {
    extern __shared__ float sm[];
    float* s_xg  = sm + SM_XG;
    float* s_qT  = sm + SM_QT;
    float* s_w   = sm + SM_W;
    float* s_gb  = sm + SM_GB;
    float* s_kv  = sm + SM_KV;
    float* s_kkT = sm + SM_KKT;
    float* s_vvT = sm + SM_VVT;
    float* s_lg  = sm + SM_LG;
    float* s_sp  = sm + SM_SP;
    float* s_c1  = sm + SM_C1;
    float* s_b1  = sm + SM_B1;
    float* s_b2  = sm + SM_B2;
    float* s_c3  = sm + SM_C3;
    float* s_b3  = sm + SM_B3;

    int tid = threadIdx.x;
    int ng  = blockIdx.x;
    int n   = ng >> 3, g = ng & 7;

    // ---- P0: loads (xg + small constants; wq read direct from gmem in P1) ----
    {
        const float4* src = (const float4*)(g_xp + ((long)n * 256 + g * 32) * 64);
        float4* dx = (float4*)s_xg;
        for (int idx = tid; idx < 512; idx += 256) dx[idx] = src[idx];
        if (tid < 128) s_c1[tid] = cw1g[tid];
        if (tid < 64) { s_b1[tid] = cb1g[tid]; s_b2[tid] = cb2g[tid]; s_c3[tid] = cw3g[tid]; }
        if (tid == 0) s_b3[0] = cb3g[0];
    }
    __syncthreads();

    // ---- P1: q projection (outer-product; warp-uniform gmem weight reads) ----
    {
        int o0 = (tid >> 5) * 8, lane = tid & 31;
        const float* wqg = g_wqT + g * 2048;
        float acc0[8], acc1[8];
        #pragma unroll
        for (int r = 0; r < 8; r++) { acc0[r] = 0.f; acc1[r] = 0.f; }
        #pragma unroll 4
        for (int c = 0; c < 32; c++) {
            float x0 = s_xg[c * 64 + lane];
            float x1 = s_xg[c * 64 + 32 + lane];
            float4 wA = __ldg((const float4*)(wqg + c * 64 + o0));
            float4 wB = __ldg((const float4*)(wqg + c * 64 + o0 + 4));
            float wv_[8] = {wA.x, wA.y, wA.z, wA.w, wB.x, wB.y, wB.z, wB.w};
            #pragma unroll
            for (int r = 0; r < 8; r++) {
                acc0[r] = fmaf(wv_[r], x0, acc0[r]);
                acc1[r] = fmaf(wv_[r], x1, acc1[r]);
            }
        }
        #pragma unroll
        for (int h4 = 0; h4 < 2; h4++) {
            float4 v0, v1;
            v0.x = acc0[h4 * 4 + 0]; v0.y = acc0[h4 * 4 + 1];
            v0.z = acc0[h4 * 4 + 2]; v0.w = acc0[h4 * 4 + 3];
            v1.x = acc1[h4 * 4 + 0]; v1.y = acc1[h4 * 4 + 1];
            v1.z = acc1[h4 * 4 + 2]; v1.w = acc1[h4 * 4 + 3];
            *(float4*)(s_qT + lane * 68 + o0 + h4 * 4)        = v0;
            *(float4*)(s_qT + (lane + 32) * 68 + o0 + h4 * 4) = v1;
        }
    }
    __syncthreads();

    // ---- P2: depthwise conv (reads qT) + GELU; concurrently load wkT|wvT ----
    {
        int ch = tid >> 2, oo = tid & 3, oy = oo >> 1, ox = oo & 1;
        float acc = 0.f;
        const float* wc = ow1 + ch * 36;
        const float* qc = s_qT + ch;       // q[ch][i] = s_qT[i*68 + ch]
        #pragma unroll
        for (int ky = 0; ky < 6; ky++) {
            int iy = oy * 4 - 1 + ky;
            if (iy < 0 || iy > 7) continue;
            #pragma unroll
            for (int kx = 0; kx < 6; kx++) {
                int ix = ox * 4 - 1 + kx;
                if (ix < 0 || ix > 7) continue;
                acc = fmaf(qc[(iy * 8 + ix) * 68], __ldg(wc + ky * 6 + kx), acc);
            }
        }
        float vs = acc + __ldg(ob1 + ch);
        s_gb[ch * 4 + oo] = 0.5f * vs * (1.f + erff(vs * 0.70710678118654752f));

        const float4* ks_ = (const float4*)(g_wkT + g * 2048);
        const float4* vs_ = (const float4*)(g_wvT + g * 2048);
        float4* dw = (float4*)s_w;
        for (int idx = tid; idx < 512; idx += 256) {
            dw[idx]       = ks_[idx];
            dw[512 + idx] = vs_[idx];
        }
    }
    __syncthreads();

    // ---- P3: offsets ----
    {
        int w = tid >> 5, lane = tid & 31;
        int j = w & 3, comp = w >> 2;
        const float* o2 = ow2 + comp * 64;
        float acc = __ldg(o2 + lane) * s_gb[lane * 4 + j]
                  + __ldg(o2 + lane + 32) * s_gb[(lane + 32) * 4 + j];
        #pragma unroll
        for (int s = 16; s > 0; s >>= 1) acc += __shfl_xor_sync(0xffffffffu, acc, s);
        if (lane == 0) {
            float base = (comp == 0) ? (float)(j & 1) : (float)(j >> 1);
            float vg = base + 4.f * tanhf(acc);
            s_sp[comp * 4 + j]     = 8.f * vg - 0.5f;
            s_sp[8 + comp * 4 + j] = 2.f * vg - 1.f;
        }
    }
    __syncthreads();

    // ---- P4: bilinear sampling ----
    if (tid < 128) {
        int c = tid >> 2, j = tid & 3;
        float sx = s_sp[j], sy = s_sp[4 + j];
        float x0f = floorf(sx), y0f = floorf(sy);
        int x0 = (int)x0f, y0 = (int)y0f;
        float fx = sx - x0f, fy = sy - y0f;
        const float* xr = s_xg + c * 64;
        float acc = 0.f;
        if (y0 >= 0 && y0 < 8) {
            if (x0 >= 0 && x0 < 8)         acc = fmaf(xr[y0 * 8 + x0],       (1.f - fx) * (1.f - fy), acc);
            if (x0 + 1 >= 0 && x0 + 1 < 8) acc = fmaf(xr[y0 * 8 + x0 + 1],   fx * (1.f - fy),         acc);
        }
        if (y0 + 1 >= 0 && y0 + 1 < 8) {
            if (x0 >= 0 && x0 < 8)         acc = fmaf(xr[(y0 + 1) * 8 + x0],     (1.f - fx) * fy, acc);
            if (x0 + 1 >= 0 && x0 + 1 < 8) acc = fmaf(xr[(y0 + 1) * 8 + x0 + 1], fx * fy,         acc);
        }
        s_kv[c * 4 + j] = acc;
    }
    __syncthreads();

    // ---- P5: k, v projections (weights [c][o]: conflict-free broadcast reads) ----
    {
        int o = tid >> 2, j = tid & 3;
        float ak = 0.f, av = 0.f;
        const float* wkc = s_w + o;          // [c][o] stride 64
        const float* wvc = s_w + 2048 + o;
        #pragma unroll 8
        for (int c = 0; c < 32; c++) {
            float kvv = s_kv[c * 4 + j];
            ak = fmaf(wkc[c * 64], kvv, ak);
            av = fmaf(wvc[c * 64], kvv, av);
        }
        s_kkT[j * 68 + o] = ak;
        s_vvT[j * 68 + o] = av;
    }
    __syncthreads();

    // ---- P6a: sim via vectorized qT/kT reads ----
    float bx, by;
    {
        int i = tid >> 2, j = tid & 3;
        const float4* qv = (const float4*)(s_qT + i * 68);
        const float4* kv = (const float4*)(s_kkT + j * 68);
        float s0 = 0.f, s1 = 0.f, s2 = 0.f, s3 = 0.f;
        #pragma unroll
        for (int t = 0; t < 16; t++) {
            float4 q4 = qv[t], k4 = kv[t];
            s0 = fmaf(q4.x, k4.x, s0);
            s1 = fmaf(q4.y, k4.y, s1);
            s2 = fmaf(q4.z, k4.z, s2);
            s3 = fmaf(q4.w, k4.w, s3);
        }
        s_lg[tid] = ((s0 + s1) + (s2 + s3)) * 0.125f;

        float qpx = (float)(i & 7) * (2.f / 7.f) - 1.f;
        float qpy = (float)(i >> 3) * (2.f / 7.f) - 1.f;
        float px = qpx - s_sp[8 + j];
        float py = qpy - s_sp[12 + j];
        bx = copysignf(log1pf(fabsf(px)), px);
        by = copysignf(log1pf(fabsf(py)), py);
    }
    __syncthreads();   // overlay region now free

    // ---- P6b: stream h1 bf16 into overlay [tid][72] via STS.128; load w2b ----
    {
        char* base = (char*)sm + tid * 144;
        #pragma unroll
        for (int u = 0; u < 8; u++) {
            float4 cx0 = *(const float4*)(s_c1 + u * 8);
            float4 cx1 = *(const float4*)(s_c1 + u * 8 + 4);
            float4 cy0 = *(const float4*)(s_c1 + 64 + u * 8);
            float4 cy1 = *(const float4*)(s_c1 + 64 + u * 8 + 4);
            float4 bb0 = *(const float4*)(s_b1 + u * 8);
            float4 bb1 = *(const float4*)(s_b1 + u * 8 + 4);
            float av_[8], cxv[8] = {cx0.x, cx0.y, cx0.z, cx0.w, cx1.x, cx1.y, cx1.z, cx1.w};
            float cyv[8] = {cy0.x, cy0.y, cy0.z, cy0.w, cy1.x, cy1.y, cy1.z, cy1.w};
            float bbv[8] = {bb0.x, bb0.y, bb0.z, bb0.w, bb1.x, bb1.y, bb1.z, bb1.w};
            #pragma unroll
            for (int e = 0; e < 8; e++)
                av_[e] = fmaf(bx, cxv[e], fmaf(by, cyv[e], bbv[e]));
            unsigned hw[4];
            #pragma unroll
            for (int v = 0; v < 4; v++) {
                __nv_bfloat162 pr = __float22bfloat162_rn(
                    make_float2(fmaxf(av_[2 * v], 0.f), fmaxf(av_[2 * v + 1], 0.f)));
                hw[v] = *(unsigned*)&pr;
            }
            uint4 pk; pk.x = hw[0]; pk.y = hw[1]; pk.z = hw[2]; pk.w = hw[3];
            *(uint4*)(base + 16 * u) = pk;
        }
        const uint4* w2s = (const uint4*)g_w2b;   // 64*72 bf16 = 576 uint4
        uint4* w2d = (uint4*)(sm + SM_W2B);
        for (int idx = tid; idx < 576; idx += 256) w2d[idx] = w2s[idx];
    }
    __syncthreads();

    // ---- P7: CPB layer2 bf16 MMA (144B strides, conflict-free fragment reads) ----
    {
        int wid = tid >> 5, lane = tid & 31;
        int p0 = wid * 32;
        const char* h1b = (const char*)sm;
        const char* w2b = (const char*)(sm + SM_W2B);
        float bias3 = s_b3[0];

        #pragma unroll
        for (int t = 0; t < 2; t++) {
            float d[8][4];
            #pragma unroll
            for (int nt = 0; nt < 8; nt++)
                #pragma unroll
                for (int r = 0; r < 4; r++) d[nt][r] = 0.f;

            #pragma unroll
            for (int ks = 0; ks < 4; ks++) {
                int cb = ks * 32 + 4 * (lane & 3);
                int row = p0 + t * 16 + (lane >> 2);
                unsigned a[4];
                a[0] = *(const unsigned*)(h1b + row * 144 + cb);
                a[1] = *(const unsigned*)(h1b + (row + 8) * 144 + cb);
                a[2] = *(const unsigned*)(h1b + row * 144 + cb + 16);
                a[3] = *(const unsigned*)(h1b + (row + 8) * 144 + cb + 16);
                #pragma unroll
                for (int nt = 0; nt < 8; nt++) {
                    int oo = nt * 8 + (lane >> 2);
                    unsigned b0 = *(const unsigned*)(w2b + oo * 144 + cb);
                    unsigned b1 = *(const unsigned*)(w2b + oo * 144 + cb + 16);
                    mma_bf16(d[nt], a, b0, b1);
                }
            }
            #pragma unroll
            for (int hf = 0; hf < 2; hf++) {
                float part = 0.f;
                #pragma unroll
                for (int nt = 0; nt < 8; nt++) {
                    int o0 = nt * 8 + 2 * (lane & 3);
                    float2 b2p = *(const float2*)(s_b2 + o0);
                    float2 c3p = *(const float2*)(s_c3 + o0);
                    float h2a = d[nt][hf * 2 + 0] + b2p.x;
                    float h2b = d[nt][hf * 2 + 1] + b2p.y;
                    part = fmaf(c3p.x, fmaxf(h2a, 0.f), part);
                    part = fmaf(c3p.y, fmaxf(h2b, 0.f), part);
                }
                part += __shfl_xor_sync(0xffffffffu, part, 1);
                part += __shfl_xor_sync(0xffffffffu, part, 2);
                if ((lane & 3) == 0) {
                    int p = p0 + t * 16 + hf * 8 + (lane >> 2);
                    s_lg[p] += part + bias3;
                }
            }
        }
    }
    __syncthreads();

    // ---- P9: per-thread softmax + out[i][d] -> g_ao [n][i][r] ----
    {
        int i = tid >> 2, dg = tid & 3, d0 = dg * 16;
        float4 lg = *(const float4*)(s_lg + i * 4);
        float m = fmaxf(fmaxf(lg.x, lg.y), fmaxf(lg.z, lg.w));
        float e0 = expf(lg.x - m), e1 = expf(lg.y - m);
        float e2 = expf(lg.z - m), e3 = expf(lg.w - m);
        float inv = 1.f / (e0 + e1 + e2 + e3);
        float a0 = e0 * inv, a1 = e1 * inv, a2 = e2 * inv, a3 = e3 * inv;

        float* dst = g_ao + ((long)n * 64 + i) * 512 + g * 64 + d0;
        const float4* v0p = (const float4*)(s_vvT + 0 * 68 + d0);
        const float4* v1p = (const float4*)(s_vvT + 1 * 68 + d0);
        const float4* v2p = (const float4*)(s_vvT + 2 * 68 + d0);
        const float4* v3p = (const float4*)(s_vvT + 3 * 68 + d0);
        #pragma unroll
        for (int w = 0; w < 4; w++) {
            float4 v0 = v0p[w], v1 = v1p[w], v2 = v2p[w], v3 = v3p[w];
            float4 o;
            o.x = cvt_tf32(a0 * v0.x + a1 * v1.x + a2 * v2.x + a3 * v3.x);
            o.y = cvt_tf32(a0 * v0.y + a1 * v1.y + a2 * v2.y + a3 * v3.y);
            o.z = cvt_tf32(a0 * v0.z + a1 * v1.z + a2 * v2.z + a3 * v3.z);
            o.w = cvt_tf32(a0 * v0.w + a1 * v1.w + a2 * v2.w + a3 * v3.w);
            *(float4*)(dst + w * 4) = o;
        }
    }
}

// ---------------- K3: output projection via tf32 MMA, cp.async double-buffered ----------------
#define K3_BUF_FLOATS (256 * 36 + 64 * 36)
#define K3_SMEM_BYTES (2 * K3_BUF_FLOATS * 4)
__global__ void __launch_bounds__(256) k3_outproj(const float* __restrict__ bo,
                                                  float* __restrict__ out) {
    extern __shared__ float sm3[];
    int n = blockIdx.x, tid = threadIdx.x;
    int wid = tid >> 5, lane = tid & 31;
    uint32_t sb_u32 = smem_u32(sm3);

    const float* wsrc = g_wo32;
    const float* asrc = g_ao + (long)n * 64 * 512;

    auto issue_slab = [&](int sl, int buf) {
        uint32_t base = sb_u32 + buf * (K3_BUF_FLOATS * 4);
        #pragma unroll
        for (int t = 0; t < 8; t++) {
            int idx = tid + t * 256;
            int c = idx >> 3, f = idx & 7;
            cpa16(base + (c * 36 + f * 4) * 4, wsrc + (long)c * 512 + sl * 32 + f * 4);
        }
        #pragma unroll
        for (int t = 0; t < 2; t++) {
            int idx = tid + t * 256;
            int i = idx >> 3, f = idx & 7;
            cpa16(base + (256 * 36 + i * 36 + f * 4) * 4, asrc + (long)i * 512 + sl * 32 + f * 4);
        }
    };

    float d[2][8][4];
    #pragma unroll
    for (int t = 0; t < 2; t++)
        #pragma unroll
        for (int nt = 0; nt < 8; nt++)
            #pragma unroll
            for (int r = 0; r < 4; r++) d[t][nt][r] = 0.f;

    issue_slab(0, 0);
    CPA_COMMIT();

    for (int s = 0; s < 16; s++) {
        if (s + 1 < 16) {
            issue_slab(s + 1, (s + 1) & 1);
            CPA_COMMIT();
            CPA_WAIT1();
        } else {
            CPA_WAIT0();
        }
        __syncthreads();

        const float* s_wb = sm3 + (s & 1) * K3_BUF_FLOATS;
        const float* s_ab = s_wb + 256 * 36;
        #pragma unroll
        for (int ks = 0; ks < 4; ks++) {
            int kk = ks * 8 + (lane & 3);
            unsigned a[2][4];
            #pragma unroll
            for (int t = 0; t < 2; t++) {
                int row = wid * 32 + t * 16 + (lane >> 2);
                a[t][0] = __float_as_uint(s_wb[row * 36 + kk]);
                a[t][1] = __float_as_uint(s_wb[(row + 8) * 36 + kk]);
                a[t][2] = __float_as_uint(s_wb[row * 36 + kk + 4]);
                a[t][3] = __float_as_uint(s_wb[(row + 8) * 36 + kk + 4]);
            }
            #pragma unroll
            for (int nt = 0; nt < 8; nt++) {
                int col = nt * 8 + (lane >> 2);
                unsigned b0 = __float_as_uint(s_ab[col * 36 + kk]);
                unsigned b1 = __float_as_uint(s_ab[col * 36 + kk + 4]);
                mma_tf32(d[0][nt], a[0], b0, b1);
                mma_tf32(d[1][nt], a[1], b0, b1);
            }
        }
        __syncthreads();
    }

    int it = n >> 7, jt = (n >> 4) & 7, b = n & 15;
    #pragma unroll
    for (int t = 0; t < 2; t++)
        #pragma unroll
        for (int hf = 0; hf < 2; hf++) {
            int c = wid * 32 + t * 16 + hf * 8 + (lane >> 2);
            float bias = __ldg(bo + c);
            #pragma unroll
            for (int nt = 0; nt < 8; nt++) {
                int i = nt * 8 + 2 * (lane & 3);
                int hh = it * 8 + (i >> 3), ww = jt * 8 + (i & 7);
                float2 v;
                v.x = d[t][nt][hf * 2 + 0] + bias;
                v.y = d[t][nt][hf * 2 + 1] + bias;
                *(float2*)(out + (((long)b * 256 + c) * 64 + hh) * 64 + ww) = v;
            }
        }
}

// ---------------- launcher ----------------
extern "C" void kernel_launch(void* const* d_in, const int* in_sizes, int n_in,
                              void* d_out, int out_size) {
    (void)in_sizes; (void)n_in; (void)out_size;
    const float* x   = (const float*)d_in[0];
    const float* lng = (const float*)d_in[1];
    const float* lnb = (const float*)d_in[2];
    const float* wq  = (const float*)d_in[3];
    const float* wk  = (const float*)d_in[4];
    const float* wv  = (const float*)d_in[5];
    const float* ow1 = (const float*)d_in[6];
    const float* ob1 = (const float*)d_in[7];
    const float* ow2 = (const float*)d_in[8];
    const float* cw1 = (const float*)d_in[9];
    const float* cb1 = (const float*)d_in[10];
    const float* cw2 = (const float*)d_in[11];
    const float* cb2 = (const float*)d_in[12];
    const float* cw3 = (const float*)d_in[13];
    const float* cb3 = (const float*)d_in[14];
    const float* wo  = (const float*)d_in[15];
    const float* bo  = (const float*)d_in[16];
    float* out = (float*)d_out;

    k0_prep<<<512, 256>>>(wo, cw2, wq, wk, wv);
    k1_ln_patch<<<2048, 256>>>(x, lng, lnb);
    cudaFuncSetAttribute(k2_attn, cudaFuncAttributeMaxDynamicSharedMemorySize, K2_SMEM_BYTES);
    k2_attn<<<NG, 256, K2_SMEM_BYTES>>>(ow1, ob1, ow2,
                                        cw1, cb1, cb2, cw3, cb3);
    cudaFuncSetAttribute(k3_outproj, cudaFuncAttributeMaxDynamicSharedMemorySize, K3_SMEM_BYTES);
    k3_outproj<<<NPATCH, 256, K3_SMEM_BYTES>>>(bo, out);
}

// round 16
// speedup vs baseline: 1.0631x; 1.0631x over previous
#include <cuda_runtime.h>
#include <cuda_bf16.h>
#include <cstdint>

// ---------------- constants ----------------
#define NPATCH 1024          // 64 tiles * B=16
#define NG     8192          // NPATCH * G

// ---------------- scratch ----------------
__device__ float g_xp[NPATCH * 256 * 64];    // normalized, patchified x  [n][c][i]
__device__ float g_ao[NPATCH * 64 * 512];    // attention output (tf32-rounded) [n][i][r]
__device__ float g_wo32[256 * 512];          // wo, tf32-rounded [c][r]
__device__ float g_wqT[8 * 32 * 64];         // wq transposed [g][c][o]
__device__ float g_wkT[8 * 32 * 64];         // wk transposed [g][c][o]
__device__ float g_wvT[8 * 32 * 64];         // wv transposed [g][c][o]
__device__ __nv_bfloat16 g_w2b[64 * 72];     // cpb w2 transposed, bf16, stride 72

// ---------------- mma helpers ----------------
static __device__ __forceinline__ void mma_bf16(float* d, const unsigned* a,
                                                unsigned b0, unsigned b1) {
    asm volatile("mma.sync.aligned.m16n8k16.row.col.f32.bf16.bf16.f32 "
        "{%0,%1,%2,%3},{%4,%5,%6,%7},{%8,%9},{%0,%1,%2,%3};"
        : "+f"(d[0]), "+f"(d[1]), "+f"(d[2]), "+f"(d[3])
        : "r"(a[0]), "r"(a[1]), "r"(a[2]), "r"(a[3]), "r"(b0), "r"(b1));
}
static __device__ __forceinline__ void mma_tf32(float* d, const unsigned* a,
                                                unsigned b0, unsigned b1) {
    asm volatile("mma.sync.aligned.m16n8k8.row.col.f32.tf32.tf32.f32 "
        "{%0,%1,%2,%3},{%4,%5,%6,%7},{%8,%9},{%0,%1,%2,%3};"
        : "+f"(d[0]), "+f"(d[1]), "+f"(d[2]), "+f"(d[3])
        : "r"(a[0]), "r"(a[1]), "r"(a[2]), "r"(a[3]), "r"(b0), "r"(b1));
}
static __device__ __forceinline__ float cvt_tf32(float x) {
    float r; asm("cvt.rna.tf32.f32 %0, %1;" : "=f"(r) : "f"(x)); return r;
}
static __device__ __forceinline__ uint32_t smem_u32(const void* p) {
    uint32_t a;
    asm("{ .reg .u64 t; cvta.to.shared.u64 t, %1; cvt.u32.u64 %0, t; }" : "=r"(a) : "l"(p));
    return a;
}
static __device__ __forceinline__ void cpa16(uint32_t dst, const void* src) {
    asm volatile("cp.async.ca.shared.global [%0], [%1], 16;" :: "r"(dst), "l"(src) : "memory");
}
#define CPA_COMMIT() asm volatile("cp.async.commit_group;" ::: "memory")
#define CPA_WAIT1()  asm volatile("cp.async.wait_group 1;" ::: "memory")
#define CPA_WAIT0()  asm volatile("cp.async.wait_group 0;" ::: "memory")

// ---------------- K1: LayerNorm+patchify (blocks<2048) | weight prep (blocks>=2048) ----------------
__global__ void __launch_bounds__(256) k1_ln_prep(const float* __restrict__ x,
                                                  const float* __restrict__ ln_g,
                                                  const float* __restrict__ ln_b,
                                                  const float* __restrict__ wo,
                                                  const float* __restrict__ cw2g,
                                                  const float* __restrict__ wq,
                                                  const float* __restrict__ wk,
                                                  const float* __restrict__ wv) {
    __shared__ float sb[256 * 32];
    __shared__ float rs[8 * 32], rq2[8 * 32];
    __shared__ float smu[32], srd[32];

    int bid  = blockIdx.x;
    int tid  = threadIdx.x;
    if (bid >= 2048) {
        // ---- weight preprocessing path (512 blocks) ----
        int idx = (bid - 2048) * 256 + tid;
        if (idx < 256 * 512) g_wo32[idx] = cvt_tf32(wo[idx]);
        if (idx < 64 * 72) {
            int o = idx / 72, k = idx % 72;
            g_w2b[idx] = (k < 64) ? __float2bfloat16(cw2g[k * 64 + o]) : __float2bfloat16(0.f);
        }
        if (idx < 8 * 64 * 32) {
            int g = idx >> 11, rem = idx & 2047, o = rem >> 5, c = rem & 31;
            int d = g * 2048 + c * 64 + o;
            g_wqT[d] = wq[idx];
            g_wkT[d] = wk[idx];
            g_wvT[d] = wv[idx];
        }
        return;
    }

    int b    = bid >> 7;
    int h    = (bid >> 1) & 63;
    int half = bid & 1;
    int w0   = half * 32;
    int wl   = tid & 31;
    int cs   = tid >> 5;

    float sum = 0.f, sq = 0.f;
    const float* xb = x + (((long)b * 256 + cs * 32) * 64 + h) * 64 + w0 + wl;
    #pragma unroll 8
    for (int m = 0; m < 32; m++) {
        float v = xb[m * 4096];
        sb[(cs * 32 + m) * 32 + wl] = v;
        sum += v; sq += v * v;
    }
    rs[cs * 32 + wl] = sum;
    rq2[cs * 32 + wl] = sq;
    __syncthreads();
    if (tid < 32) {
        float S = 0.f, Q = 0.f;
        #pragma unroll
        for (int s = 0; s < 8; s++) { S += rs[s * 32 + tid]; Q += rq2[s * 32 + tid]; }
        float mu  = S * (1.f / 256.f);
        float var = Q * (1.f / 256.f) - mu * mu;
        smu[tid] = mu;
        srd[tid] = rsqrtf(var + 1e-6f);
    }
    __syncthreads();
    float mu = smu[wl], rd = srd[wl];
    int w  = w0 + wl;
    int it = h >> 3, p = h & 7, jt = w >> 3, q = w & 7;
    int n  = it * 128 + jt * 16 + b;
    float* dst = g_xp + (long)n * 256 * 64 + p * 8 + q;
    #pragma unroll 8
    for (int m = 0; m < 32; m++) {
        int c = cs * 32 + m;
        float v = (sb[c * 32 + wl] - mu) * rd * __ldg(ln_g + c) + __ldg(ln_b + c);
        dst[c * 64] = v;
    }
}

// ---------------- K2: per-(n,g) deformable attention ----------------
#define SM_XG   0        // 2048
#define SM_W    2048     // 4096 (wqT [c][o], then wkT|wvT [c][o])
#define SM_QT   6144     // 64*68 = 4352, ends 10496
#define SM_W2B  9216     // overlay (P6b+): 64 rows x 36 floats, ends 11520
#define SM_GB   11520    // 256
#define SM_KV   11776    // 128
#define SM_KKT  11904    // 4*68 = 272
#define SM_VVT  12176    // 4*68 = 272
#define SM_LG   12448    // 256
#define SM_SP   12704    // 16
#define SM_C1   12720    // 128
#define SM_B1   12848    // 64
#define SM_B2   12912    // 64
#define SM_C3   12976    // 64
#define SM_B3   13040    // 4
#define K2_SMEM_BYTES (13044 * 4)

__global__ void __launch_bounds__(256, 4) k2_attn(
    const float* __restrict__ ow1, const float* __restrict__ ob1, const float* __restrict__ ow2,
    const float* __restrict__ cw1g, const float* __restrict__ cb1g,
    const float* __restrict__ cb2g,
    const float* __restrict__ cw3g, const float* __restrict__ cb3g) {
    extern __shared__ float sm[];
    float* s_xg  = sm + SM_XG;
    float* s_qT  = sm + SM_QT;
    float* s_w   = sm + SM_W;
    float* s_gb  = sm + SM_GB;
    float* s_kv  = sm + SM_KV;
    float* s_kkT = sm + SM_KKT;
    float* s_vvT = sm + SM_VVT;
    float* s_lg  = sm + SM_LG;
    float* s_sp  = sm + SM_SP;
    float* s_c1  = sm + SM_C1;
    float* s_b1  = sm + SM_B1;
    float* s_b2  = sm + SM_B2;
    float* s_c3  = sm + SM_C3;
    float* s_b3  = sm + SM_B3;

    int tid = threadIdx.x;
    int ng  = blockIdx.x;
    int n   = ng >> 3, g = ng & 7;

    // ---- P0: loads ----
    {
        const float4* src = (const float4*)(g_xp + ((long)n * 256 + g * 32) * 64);
        float4* dx = (float4*)s_xg;
        for (int idx = tid; idx < 512; idx += 256) dx[idx] = src[idx];
        const float4* wqs = (const float4*)(g_wqT + g * 2048);
        float4* dw = (float4*)s_w;
        for (int idx = tid; idx < 512; idx += 256) dw[idx] = wqs[idx];
        if (tid < 128) s_c1[tid] = cw1g[tid];
        if (tid < 64) { s_b1[tid] = cb1g[tid]; s_b2[tid] = cb2g[tid]; s_c3[tid] = cw3g[tid]; }
        if (tid == 0) s_b3[0] = cb3g[0];
    }
    __syncthreads();

    // ---- P1: q projection (outer-product; broadcast float4 weights [c][o]) ----
    {
        int o0 = (tid >> 5) * 8, lane = tid & 31;
        float acc0[8], acc1[8];
        #pragma unroll
        for (int r = 0; r < 8; r++) { acc0[r] = 0.f; acc1[r] = 0.f; }
        #pragma unroll 4
        for (int c = 0; c < 32; c++) {
            float x0 = s_xg[c * 64 + lane];
            float x1 = s_xg[c * 64 + 32 + lane];
            float4 wA = *(const float4*)(s_w + c * 64 + o0);
            float4 wB = *(const float4*)(s_w + c * 64 + o0 + 4);
            float wv_[8] = {wA.x, wA.y, wA.z, wA.w, wB.x, wB.y, wB.z, wB.w};
            #pragma unroll
            for (int r = 0; r < 8; r++) {
                acc0[r] = fmaf(wv_[r], x0, acc0[r]);
                acc1[r] = fmaf(wv_[r], x1, acc1[r]);
            }
        }
        #pragma unroll
        for (int h4 = 0; h4 < 2; h4++) {
            float4 v0, v1;
            v0.x = acc0[h4 * 4 + 0]; v0.y = acc0[h4 * 4 + 1];
            v0.z = acc0[h4 * 4 + 2]; v0.w = acc0[h4 * 4 + 3];
            v1.x = acc1[h4 * 4 + 0]; v1.y = acc1[h4 * 4 + 1];
            v1.z = acc1[h4 * 4 + 2]; v1.w = acc1[h4 * 4 + 3];
            *(float4*)(s_qT + lane * 68 + o0 + h4 * 4)        = v0;
            *(float4*)(s_qT + (lane + 32) * 68 + o0 + h4 * 4) = v1;
        }
    }
    __syncthreads();

    // ---- P2: depthwise conv (reads qT) + GELU; concurrently load wkT|wvT ----
    {
        int ch = tid >> 2, oo = tid & 3, oy = oo >> 1, ox = oo & 1;
        float acc = 0.f;
        const float* wc = ow1 + ch * 36;
        const float* qc = s_qT + ch;       // q[ch][i] = s_qT[i*68 + ch]
        #pragma unroll
        for (int ky = 0; ky < 6; ky++) {
            int iy = oy * 4 - 1 + ky;
            if (iy < 0 || iy > 7) continue;
            #pragma unroll
            for (int kx = 0; kx < 6; kx++) {
                int ix = ox * 4 - 1 + kx;
                if (ix < 0 || ix > 7) continue;
                acc = fmaf(qc[(iy * 8 + ix) * 68], __ldg(wc + ky * 6 + kx), acc);
            }
        }
        float vs = acc + __ldg(ob1 + ch);
        s_gb[ch * 4 + oo] = 0.5f * vs * (1.f + erff(vs * 0.70710678118654752f));

        const float4* ks_ = (const float4*)(g_wkT + g * 2048);
        const float4* vs_ = (const float4*)(g_wvT + g * 2048);
        float4* dw = (float4*)s_w;
        for (int idx = tid; idx < 512; idx += 256) {
            dw[idx]       = ks_[idx];
            dw[512 + idx] = vs_[idx];
        }
    }
    __syncthreads();

    // ---- P3: offsets ----
    {
        int w = tid >> 5, lane = tid & 31;
        int j = w & 3, comp = w >> 2;
        const float* o2 = ow2 + comp * 64;
        float acc = __ldg(o2 + lane) * s_gb[lane * 4 + j]
                  + __ldg(o2 + lane + 32) * s_gb[(lane + 32) * 4 + j];
        #pragma unroll
        for (int s = 16; s > 0; s >>= 1) acc += __shfl_xor_sync(0xffffffffu, acc, s);
        if (lane == 0) {
            float base = (comp == 0) ? (float)(j & 1) : (float)(j >> 1);
            float vg = base + 4.f * tanhf(acc);
            s_sp[comp * 4 + j]     = 8.f * vg - 0.5f;
            s_sp[8 + comp * 4 + j] = 2.f * vg - 1.f;
        }
    }
    __syncthreads();

    // ---- P4: bilinear sampling ----
    if (tid < 128) {
        int c = tid >> 2, j = tid & 3;
        float sx = s_sp[j], sy = s_sp[4 + j];
        float x0f = floorf(sx), y0f = floorf(sy);
        int x0 = (int)x0f, y0 = (int)y0f;
        float fx = sx - x0f, fy = sy - y0f;
        const float* xr = s_xg + c * 64;
        float acc = 0.f;
        if (y0 >= 0 && y0 < 8) {
            if (x0 >= 0 && x0 < 8)         acc = fmaf(xr[y0 * 8 + x0],       (1.f - fx) * (1.f - fy), acc);
            if (x0 + 1 >= 0 && x0 + 1 < 8) acc = fmaf(xr[y0 * 8 + x0 + 1],   fx * (1.f - fy),         acc);
        }
        if (y0 + 1 >= 0 && y0 + 1 < 8) {
            if (x0 >= 0 && x0 < 8)         acc = fmaf(xr[(y0 + 1) * 8 + x0],     (1.f - fx) * fy, acc);
            if (x0 + 1 >= 0 && x0 + 1 < 8) acc = fmaf(xr[(y0 + 1) * 8 + x0 + 1], fx * fy,         acc);
        }
        s_kv[c * 4 + j] = acc;
    }
    __syncthreads();

    // ---- P5: k, v projections (weights [c][o]: conflict-free broadcast reads) ----
    {
        int o = tid >> 2, j = tid & 3;
        float ak = 0.f, av = 0.f;
        const float* wkc = s_w + o;          // [c][o] stride 64
        const float* wvc = s_w + 2048 + o;
        #pragma unroll 8
        for (int c = 0; c < 32; c++) {
            float kvv = s_kv[c * 4 + j];
            ak = fmaf(wkc[c * 64], kvv, ak);
            av = fmaf(wvc[c * 64], kvv, av);
        }
        s_kkT[j * 68 + o] = ak;
        s_vvT[j * 68 + o] = av;
    }
    __syncthreads();

    // ---- P6a: sim via vectorized qT/kT reads ----
    float bx, by;
    {
        int i = tid >> 2, j = tid & 3;
        const float4* qv = (const float4*)(s_qT + i * 68);
        const float4* kv = (const float4*)(s_kkT + j * 68);
        float s0 = 0.f, s1 = 0.f, s2 = 0.f, s3 = 0.f;
        #pragma unroll
        for (int t = 0; t < 16; t++) {
            float4 q4 = qv[t], k4 = kv[t];
            s0 = fmaf(q4.x, k4.x, s0);
            s1 = fmaf(q4.y, k4.y, s1);
            s2 = fmaf(q4.z, k4.z, s2);
            s3 = fmaf(q4.w, k4.w, s3);
        }
        s_lg[tid] = ((s0 + s1) + (s2 + s3)) * 0.125f;

        float qpx = (float)(i & 7) * (2.f / 7.f) - 1.f;
        float qpy = (float)(i >> 3) * (2.f / 7.f) - 1.f;
        float px = qpx - s_sp[8 + j];
        float py = qpy - s_sp[12 + j];
        bx = copysignf(log1pf(fabsf(px)), px);
        by = copysignf(log1pf(fabsf(py)), py);
    }
    __syncthreads();   // overlay region now free

    // ---- P6b: stream h1 bf16 into overlay [tid][72] via STS.128; load w2b ----
    {
        char* base = (char*)sm + tid * 144;
        #pragma unroll
        for (int u = 0; u < 8; u++) {
            float4 cx0 = *(const float4*)(s_c1 + u * 8);
            float4 cx1 = *(const float4*)(s_c1 + u * 8 + 4);
            float4 cy0 = *(const float4*)(s_c1 + 64 + u * 8);
            float4 cy1 = *(const float4*)(s_c1 + 64 + u * 8 + 4);
            float4 bb0 = *(const float4*)(s_b1 + u * 8);
            float4 bb1 = *(const float4*)(s_b1 + u * 8 + 4);
            float av_[8], cxv[8] = {cx0.x, cx0.y, cx0.z, cx0.w, cx1.x, cx1.y, cx1.z, cx1.w};
            float cyv[8] = {cy0.x, cy0.y, cy0.z, cy0.w, cy1.x, cy1.y, cy1.z, cy1.w};
            float bbv[8] = {bb0.x, bb0.y, bb0.z, bb0.w, bb1.x, bb1.y, bb1.z, bb1.w};
            #pragma unroll
            for (int e = 0; e < 8; e++)
                av_[e] = fmaf(bx, cxv[e], fmaf(by, cyv[e], bbv[e]));
            unsigned hw[4];
            #pragma unroll
            for (int v = 0; v < 4; v++) {
                __nv_bfloat162 pr = __float22bfloat162_rn(
                    make_float2(fmaxf(av_[2 * v], 0.f), fmaxf(av_[2 * v + 1], 0.f)));
                hw[v] = *(unsigned*)&pr;
            }
            uint4 pk; pk.x = hw[0]; pk.y = hw[1]; pk.z = hw[2]; pk.w = hw[3];
            *(uint4*)(base + 16 * u) = pk;
        }
        const uint4* w2s = (const uint4*)g_w2b;   // 64*72 bf16 = 576 uint4
        uint4* w2d = (uint4*)(sm + SM_W2B);
        for (int idx = tid; idx < 576; idx += 256) w2d[idx] = w2s[idx];
    }
    __syncthreads();

    // ---- P7: CPB layer2 bf16 MMA (144B strides, conflict-free fragment reads) ----
    {
        int wid = tid >> 5, lane = tid & 31;
        int p0 = wid * 32;
        const char* h1b = (const char*)sm;
        const char* w2b = (const char*)(sm + SM_W2B);
        float bias3 = s_b3[0];

        #pragma unroll
        for (int t = 0; t < 2; t++) {
            float d[8][4];
            #pragma unroll
            for (int nt = 0; nt < 8; nt++)
                #pragma unroll
                for (int r = 0; r < 4; r++) d[nt][r] = 0.f;

            #pragma unroll
            for (int ks = 0; ks < 4; ks++) {
                int cb = ks * 32 + 4 * (lane & 3);
                int row = p0 + t * 16 + (lane >> 2);
                unsigned a[4];
                a[0] = *(const unsigned*)(h1b + row * 144 + cb);
                a[1] = *(const unsigned*)(h1b + (row + 8) * 144 + cb);
                a[2] = *(const unsigned*)(h1b + row * 144 + cb + 16);
                a[3] = *(const unsigned*)(h1b + (row + 8) * 144 + cb + 16);
                #pragma unroll
                for (int nt = 0; nt < 8; nt++) {
                    int oo = nt * 8 + (lane >> 2);
                    unsigned b0 = *(const unsigned*)(w2b + oo * 144 + cb);
                    unsigned b1 = *(const unsigned*)(w2b + oo * 144 + cb + 16);
                    mma_bf16(d[nt], a, b0, b1);
                }
            }
            #pragma unroll
            for (int hf = 0; hf < 2; hf++) {
                float part = 0.f;
                #pragma unroll
                for (int nt = 0; nt < 8; nt++) {
                    int o0 = nt * 8 + 2 * (lane & 3);
                    float2 b2p = *(const float2*)(s_b2 + o0);
                    float2 c3p = *(const float2*)(s_c3 + o0);
                    float h2a = d[nt][hf * 2 + 0] + b2p.x;
                    float h2b = d[nt][hf * 2 + 1] + b2p.y;
                    part = fmaf(c3p.x, fmaxf(h2a, 0.f), part);
                    part = fmaf(c3p.y, fmaxf(h2b, 0.f), part);
                }
                part += __shfl_xor_sync(0xffffffffu, part, 1);
                part += __shfl_xor_sync(0xffffffffu, part, 2);
                if ((lane & 3) == 0) {
                    int p = p0 + t * 16 + hf * 8 + (lane >> 2);
                    s_lg[p] += part + bias3;
                }
            }
        }
    }
    __syncthreads();

    // ---- P9: per-thread softmax + out[i][d] -> g_ao [n][i][r] ----
    {
        int i = tid >> 2, dg = tid & 3, d0 = dg * 16;
        float4 lg = *(const float4*)(s_lg + i * 4);
        float m = fmaxf(fmaxf(lg.x, lg.y), fmaxf(lg.z, lg.w));
        float e0 = expf(lg.x - m), e1 = expf(lg.y - m);
        float e2 = expf(lg.z - m), e3 = expf(lg.w - m);
        float inv = 1.f / (e0 + e1 + e2 + e3);
        float a0 = e0 * inv, a1 = e1 * inv, a2 = e2 * inv, a3 = e3 * inv;

        float* dst = g_ao + ((long)n * 64 + i) * 512 + g * 64 + d0;
        const float4* v0p = (const float4*)(s_vvT + 0 * 68 + d0);
        const float4* v1p = (const float4*)(s_vvT + 1 * 68 + d0);
        const float4* v2p = (const float4*)(s_vvT + 2 * 68 + d0);
        const float4* v3p = (const float4*)(s_vvT + 3 * 68 + d0);
        #pragma unroll
        for (int w = 0; w < 4; w++) {
            float4 v0 = v0p[w], v1 = v1p[w], v2 = v2p[w], v3 = v3p[w];
            float4 o;
            o.x = cvt_tf32(a0 * v0.x + a1 * v1.x + a2 * v2.x + a3 * v3.x);
            o.y = cvt_tf32(a0 * v0.y + a1 * v1.y + a2 * v2.y + a3 * v3.y);
            o.z = cvt_tf32(a0 * v0.z + a1 * v1.z + a2 * v2.z + a3 * v3.z);
            o.w = cvt_tf32(a0 * v0.w + a1 * v1.w + a2 * v2.w + a3 * v3.w);
            *(float4*)(dst + w * 4) = o;
        }
    }
}

// ---------------- K3: output projection via tf32 MMA, cp.async double-buffered ----------------
#define K3_BUF_FLOATS (256 * 36 + 64 * 36)
#define K3_SMEM_BYTES (2 * K3_BUF_FLOATS * 4)
__global__ void __launch_bounds__(256) k3_outproj(const float* __restrict__ bo,
                                                  float* __restrict__ out) {
    extern __shared__ float sm3[];
    int n = blockIdx.x, tid = threadIdx.x;
    int wid = tid >> 5, lane = tid & 31;
    uint32_t sb_u32 = smem_u32(sm3);

    const float* wsrc = g_wo32;
    const float* asrc = g_ao + (long)n * 64 * 512;

    auto issue_slab = [&](int sl, int buf) {
        uint32_t base = sb_u32 + buf * (K3_BUF_FLOATS * 4);
        #pragma unroll
        for (int t = 0; t < 8; t++) {
            int idx = tid + t * 256;
            int c = idx >> 3, f = idx & 7;
            cpa16(base + (c * 36 + f * 4) * 4, wsrc + (long)c * 512 + sl * 32 + f * 4);
        }
        #pragma unroll
        for (int t = 0; t < 2; t++) {
            int idx = tid + t * 256;
            int i = idx >> 3, f = idx & 7;
            cpa16(base + (256 * 36 + i * 36 + f * 4) * 4, asrc + (long)i * 512 + sl * 32 + f * 4);
        }
    };

    float d[2][8][4];
    #pragma unroll
    for (int t = 0; t < 2; t++)
        #pragma unroll
        for (int nt = 0; nt < 8; nt++)
            #pragma unroll
            for (int r = 0; r < 4; r++) d[t][nt][r] = 0.f;

    issue_slab(0, 0);
    CPA_COMMIT();

    for (int s = 0; s < 16; s++) {
        if (s + 1 < 16) {
            issue_slab(s + 1, (s + 1) & 1);
            CPA_COMMIT();
            CPA_WAIT1();
        } else {
            CPA_WAIT0();
        }
        __syncthreads();

        const float* s_wb = sm3 + (s & 1) * K3_BUF_FLOATS;
        const float* s_ab = s_wb + 256 * 36;
        #pragma unroll
        for (int ks = 0; ks < 4; ks++) {
            int kk = ks * 8 + (lane & 3);
            unsigned a[2][4];
            #pragma unroll
            for (int t = 0; t < 2; t++) {
                int row = wid * 32 + t * 16 + (lane >> 2);
                a[t][0] = __float_as_uint(s_wb[row * 36 + kk]);
                a[t][1] = __float_as_uint(s_wb[(row + 8) * 36 + kk]);
                a[t][2] = __float_as_uint(s_wb[row * 36 + kk + 4]);
                a[t][3] = __float_as_uint(s_wb[(row + 8) * 36 + kk + 4]);
            }
            #pragma unroll
            for (int nt = 0; nt < 8; nt++) {
                int col = nt * 8 + (lane >> 2);
                unsigned b0 = __float_as_uint(s_ab[col * 36 + kk]);
                unsigned b1 = __float_as_uint(s_ab[col * 36 + kk + 4]);
                mma_tf32(d[0][nt], a[0], b0, b1);
                mma_tf32(d[1][nt], a[1], b0, b1);
            }
        }
        __syncthreads();
    }

    int it = n >> 7, jt = (n >> 4) & 7, b = n & 15;
    #pragma unroll
    for (int t = 0; t < 2; t++)
        #pragma unroll
        for (int hf = 0; hf < 2; hf++) {
            int c = wid * 32 + t * 16 + hf * 8 + (lane >> 2);
            float bias = __ldg(bo + c);
            #pragma unroll
            for (int nt = 0; nt < 8; nt++) {
                int i = nt * 8 + 2 * (lane & 3);
                int hh = it * 8 + (i >> 3), ww = jt * 8 + (i & 7);
                float2 v;
                v.x = d[t][nt][hf * 2 + 0] + bias;
                v.y = d[t][nt][hf * 2 + 1] + bias;
                *(float2*)(out + (((long)b * 256 + c) * 64 + hh) * 64 + ww) = v;
            }
        }
}

// ---------------- launcher ----------------
extern "C" void kernel_launch(void* const* d_in, const int* in_sizes, int n_in,
                              void* d_out, int out_size) {
    (void)in_sizes; (void)n_in; (void)out_size;
    const float* x   = (const float*)d_in[0];
    const float* lng = (const float*)d_in[1];
    const float* lnb = (const float*)d_in[2];
    const float* wq  = (const float*)d_in[3];
    const float* wk  = (const float*)d_in[4];
    const float* wv  = (const float*)d_in[5];
    const float* ow1 = (const float*)d_in[6];
    const float* ob1 = (const float*)d_in[7];
    const float* ow2 = (const float*)d_in[8];
    const float* cw1 = (const float*)d_in[9];
    const float* cb1 = (const float*)d_in[10];
    const float* cw2 = (const float*)d_in[11];
    const float* cb2 = (const float*)d_in[12];
    const float* cw3 = (const float*)d_in[13];
    const float* cb3 = (const float*)d_in[14];
    const float* wo  = (const float*)d_in[15];
    const float* bo  = (const float*)d_in[16];
    float* out = (float*)d_out;

    k1_ln_prep<<<2560, 256>>>(x, lng, lnb, wo, cw2, wq, wk, wv);
    cudaFuncSetAttribute(k2_attn, cudaFuncAttributeMaxDynamicSharedMemorySize, K2_SMEM_BYTES);
    k2_attn<<<NG, 256, K2_SMEM_BYTES>>>(ow1, ob1, ow2,
                                        cw1, cb1, cb2, cw3, cb3);
    cudaFuncSetAttribute(k3_outproj, cudaFuncAttributeMaxDynamicSharedMemorySize, K3_SMEM_BYTES);
    k3_outproj<<<NPATCH, 256, K3_SMEM_BYTES>>>(bo, out);
}

// round 17
// speedup vs baseline: 1.0695x; 1.0060x over previous
#include <cuda_runtime.h>
#include <cuda_bf16.h>
#include <cstdint>

// ---------------- constants ----------------
#define NPATCH 1024          // 64 tiles * B=16
#define NG     8192          // NPATCH * G

// ---------------- scratch ----------------
__device__ float g_xp[NPATCH * 256 * 64];    // normalized, patchified x  [n][c][i]
__device__ float g_ao[NPATCH * 64 * 512];    // attention output (tf32-rounded) [n][i][r]
__device__ float g_wo32[256 * 512];          // wo, tf32-rounded [c][r]
__device__ float g_wqT[8 * 32 * 64];         // wq transposed [g][c][o]
__device__ float g_wkT[8 * 32 * 64];         // wk transposed [g][c][o]
__device__ float g_wvT[8 * 32 * 64];         // wv transposed [g][c][o]
__device__ __nv_bfloat16 g_w2b[64 * 72];     // cpb w2 transposed, bf16, stride 72

// ---------------- packed f32x2 helpers (sm_103a) ----------------
static __device__ __forceinline__ float2 ffma2(float2 a, float2 b, float2 c) {
    union U { float2 f; unsigned long long u; };
    U A, B, C, D;
    A.f = a; B.f = b; C.f = c;
    asm("fma.rn.f32x2 %0, %1, %2, %3;" : "=l"(D.u) : "l"(A.u), "l"(B.u), "l"(C.u));
    return D.f;
}
static __device__ __forceinline__ float2 fmul2(float2 a, float2 b) {
    union U { float2 f; unsigned long long u; };
    U A, B, D;
    A.f = a; B.f = b;
    asm("mul.rn.f32x2 %0, %1, %2;" : "=l"(D.u) : "l"(A.u), "l"(B.u));
    return D.f;
}

// ---------------- mma helpers ----------------
static __device__ __forceinline__ void mma_bf16(float* d, const unsigned* a,
                                                unsigned b0, unsigned b1) {
    asm volatile("mma.sync.aligned.m16n8k16.row.col.f32.bf16.bf16.f32 "
        "{%0,%1,%2,%3},{%4,%5,%6,%7},{%8,%9},{%0,%1,%2,%3};"
        : "+f"(d[0]), "+f"(d[1]), "+f"(d[2]), "+f"(d[3])
        : "r"(a[0]), "r"(a[1]), "r"(a[2]), "r"(a[3]), "r"(b0), "r"(b1));
}
static __device__ __forceinline__ void mma_tf32(float* d, const unsigned* a,
                                                unsigned b0, unsigned b1) {
    asm volatile("mma.sync.aligned.m16n8k8.row.col.f32.tf32.tf32.f32 "
        "{%0,%1,%2,%3},{%4,%5,%6,%7},{%8,%9},{%0,%1,%2,%3};"
        : "+f"(d[0]), "+f"(d[1]), "+f"(d[2]), "+f"(d[3])
        : "r"(a[0]), "r"(a[1]), "r"(a[2]), "r"(a[3]), "r"(b0), "r"(b1));
}
static __device__ __forceinline__ float cvt_tf32(float x) {
    float r; asm("cvt.rna.tf32.f32 %0, %1;" : "=f"(r) : "f"(x)); return r;
}
static __device__ __forceinline__ uint32_t smem_u32(const void* p) {
    uint32_t a;
    asm("{ .reg .u64 t; cvta.to.shared.u64 t, %1; cvt.u32.u64 %0, t; }" : "=r"(a) : "l"(p));
    return a;
}
static __device__ __forceinline__ void cpa16(uint32_t dst, const void* src) {
    asm volatile("cp.async.ca.shared.global [%0], [%1], 16;" :: "r"(dst), "l"(src) : "memory");
}
#define CPA_COMMIT() asm volatile("cp.async.commit_group;" ::: "memory")
#define CPA_WAIT1()  asm volatile("cp.async.wait_group 1;" ::: "memory")
#define CPA_WAIT0()  asm volatile("cp.async.wait_group 0;" ::: "memory")

// ---------------- K1: LayerNorm+patchify (blocks<2048) | weight prep (blocks>=2048) ----------------
__global__ void __launch_bounds__(256) k1_ln_prep(const float* __restrict__ x,
                                                  const float* __restrict__ ln_g,
                                                  const float* __restrict__ ln_b,
                                                  const float* __restrict__ wo,
                                                  const float* __restrict__ cw2g,
                                                  const float* __restrict__ wq,
                                                  const float* __restrict__ wk,
                                                  const float* __restrict__ wv) {
    __shared__ float sb[256 * 32];
    __shared__ float rs[8 * 32], rq2[8 * 32];
    __shared__ float smu[32], srd[32];

    int bid  = blockIdx.x;
    int tid  = threadIdx.x;
    if (bid >= 2048) {
        int idx = (bid - 2048) * 256 + tid;
        if (idx < 256 * 512) g_wo32[idx] = cvt_tf32(wo[idx]);
        if (idx < 64 * 72) {
            int o = idx / 72, k = idx % 72;
            g_w2b[idx] = (k < 64) ? __float2bfloat16(cw2g[k * 64 + o]) : __float2bfloat16(0.f);
        }
        if (idx < 8 * 64 * 32) {
            int g = idx >> 11, rem = idx & 2047, o = rem >> 5, c = rem & 31;
            int d = g * 2048 + c * 64 + o;
            g_wqT[d] = wq[idx];
            g_wkT[d] = wk[idx];
            g_wvT[d] = wv[idx];
        }
        return;
    }

    int b    = bid >> 7;
    int h    = (bid >> 1) & 63;
    int half = bid & 1;
    int w0   = half * 32;
    int wl   = tid & 31;
    int cs   = tid >> 5;

    float sum = 0.f, sq = 0.f;
    const float* xb = x + (((long)b * 256 + cs * 32) * 64 + h) * 64 + w0 + wl;
    #pragma unroll 8
    for (int m = 0; m < 32; m++) {
        float v = xb[m * 4096];
        sb[(cs * 32 + m) * 32 + wl] = v;
        sum += v; sq += v * v;
    }
    rs[cs * 32 + wl] = sum;
    rq2[cs * 32 + wl] = sq;
    __syncthreads();
    if (tid < 32) {
        float S = 0.f, Q = 0.f;
        #pragma unroll
        for (int s = 0; s < 8; s++) { S += rs[s * 32 + tid]; Q += rq2[s * 32 + tid]; }
        float mu  = S * (1.f / 256.f);
        float var = Q * (1.f / 256.f) - mu * mu;
        smu[tid] = mu;
        srd[tid] = rsqrtf(var + 1e-6f);
    }
    __syncthreads();
    float mu = smu[wl], rd = srd[wl];
    int w  = w0 + wl;
    int it = h >> 3, p = h & 7, jt = w >> 3, q = w & 7;
    int n  = it * 128 + jt * 16 + b;
    float* dst = g_xp + (long)n * 256 * 64 + p * 8 + q;
    #pragma unroll 8
    for (int m = 0; m < 32; m++) {
        int c = cs * 32 + m;
        float v = (sb[c * 32 + wl] - mu) * rd * __ldg(ln_g + c) + __ldg(ln_b + c);
        dst[c * 64] = v;
    }
}

// ---------------- K2: per-(n,g) deformable attention ----------------
#define SM_XG   0        // 2048
#define SM_W    2048     // 4096 (wqT [c][o], then wkT|wvT [c][o])
#define SM_QT   6144     // 64*68 = 4352, ends 10496
#define SM_W2B  9216     // overlay (P6b+): 64 rows x 36 floats, ends 11520
#define SM_GB   11520    // 256
#define SM_KV   11776    // 128
#define SM_KKT  11904    // 4*68 = 272
#define SM_VVT  12176    // 4*68 = 272
#define SM_LG   12448    // 256
#define SM_SP   12704    // 16
#define SM_C1   12720    // 128
#define SM_B1   12848    // 64
#define SM_B2   12912    // 64
#define SM_C3   12976    // 64
#define SM_B3   13040    // 4
#define K2_SMEM_BYTES (13044 * 4)

__global__ void __launch_bounds__(256, 4) k2_attn(
    const float* __restrict__ ow1, const float* __restrict__ ob1, const float* __restrict__ ow2,
    const float* __restrict__ cw1g, const float* __restrict__ cb1g,
    const float* __restrict__ cb2g,
    const float* __restrict__ cw3g, const float* __restrict__ cb3g) {
    extern __shared__ float sm[];
    float* s_xg  = sm + SM_XG;
    float* s_qT  = sm + SM_QT;
    float* s_w   = sm + SM_W;
    float* s_gb  = sm + SM_GB;
    float* s_kv  = sm + SM_KV;
    float* s_kkT = sm + SM_KKT;
    float* s_vvT = sm + SM_VVT;
    float* s_lg  = sm + SM_LG;
    float* s_sp  = sm + SM_SP;
    float* s_c1  = sm + SM_C1;
    float* s_b1  = sm + SM_B1;
    float* s_b2  = sm + SM_B2;
    float* s_c3  = sm + SM_C3;
    float* s_b3  = sm + SM_B3;

    int tid = threadIdx.x;
    int ng  = blockIdx.x;
    int n   = ng >> 3, g = ng & 7;

    // ---- P0: loads ----
    {
        const float4* src = (const float4*)(g_xp + ((long)n * 256 + g * 32) * 64);
        float4* dx = (float4*)s_xg;
        for (int idx = tid; idx < 512; idx += 256) dx[idx] = src[idx];
        const float4* wqs = (const float4*)(g_wqT + g * 2048);
        float4* dw = (float4*)s_w;
        for (int idx = tid; idx < 512; idx += 256) dw[idx] = wqs[idx];
        if (tid < 128) s_c1[tid] = cw1g[tid];
        if (tid < 64) { s_b1[tid] = cb1g[tid]; s_b2[tid] = cb2g[tid]; s_c3[tid] = cw3g[tid]; }
        if (tid == 0) s_b3[0] = cb3g[0];
    }
    __syncthreads();

    // ---- P1: q projection (outer-product; f32x2 packed along o-pairs) ----
    {
        int o0 = (tid >> 5) * 8, lane = tid & 31;
        float2 acc[4][2];   // [o-pair][i-half]: (q[o0+2p], q[o0+2p+1]) for i=lane / lane+32
        #pragma unroll
        for (int p = 0; p < 4; p++) {
            acc[p][0].x = 0.f; acc[p][0].y = 0.f;
            acc[p][1].x = 0.f; acc[p][1].y = 0.f;
        }
        #pragma unroll 4
        for (int c = 0; c < 32; c++) {
            float x0 = s_xg[c * 64 + lane];
            float x1 = s_xg[c * 64 + 32 + lane];
            float2 x0p; x0p.x = x0; x0p.y = x0;
            float2 x1p; x1p.x = x1; x1p.y = x1;
            float4 wA = *(const float4*)(s_w + c * 64 + o0);
            float4 wB = *(const float4*)(s_w + c * 64 + o0 + 4);
            float2 w01; w01.x = wA.x; w01.y = wA.y;
            float2 w23; w23.x = wA.z; w23.y = wA.w;
            float2 w45; w45.x = wB.x; w45.y = wB.y;
            float2 w67; w67.x = wB.z; w67.y = wB.w;
            acc[0][0] = ffma2(w01, x0p, acc[0][0]);
            acc[0][1] = ffma2(w01, x1p, acc[0][1]);
            acc[1][0] = ffma2(w23, x0p, acc[1][0]);
            acc[1][1] = ffma2(w23, x1p, acc[1][1]);
            acc[2][0] = ffma2(w45, x0p, acc[2][0]);
            acc[2][1] = ffma2(w45, x1p, acc[2][1]);
            acc[3][0] = ffma2(w67, x0p, acc[3][0]);
            acc[3][1] = ffma2(w67, x1p, acc[3][1]);
        }
        #pragma unroll
        for (int h = 0; h < 2; h++) {
            float4 v0, v1;
            v0.x = acc[0][h].x; v0.y = acc[0][h].y;
            v0.z = acc[1][h].x; v0.w = acc[1][h].y;
            v1.x = acc[2][h].x; v1.y = acc[2][h].y;
            v1.z = acc[3][h].x; v1.w = acc[3][h].y;
            int row = lane + h * 32;
            *(float4*)(s_qT + row * 68 + o0)     = v0;
            *(float4*)(s_qT + row * 68 + o0 + 4) = v1;
        }
    }
    __syncthreads();

    // ---- P2: depthwise conv (reads qT) + GELU; concurrently load wkT|wvT ----
    {
        int ch = tid >> 2, oo = tid & 3, oy = oo >> 1, ox = oo & 1;
        float acc = 0.f;
        const float* wc = ow1 + ch * 36;
        const float* qc = s_qT + ch;       // q[ch][i] = s_qT[i*68 + ch]
        #pragma unroll
        for (int ky = 0; ky < 6; ky++) {
            int iy = oy * 4 - 1 + ky;
            if (iy < 0 || iy > 7) continue;
            #pragma unroll
            for (int kx = 0; kx < 6; kx++) {
                int ix = ox * 4 - 1 + kx;
                if (ix < 0 || ix > 7) continue;
                acc = fmaf(qc[(iy * 8 + ix) * 68], __ldg(wc + ky * 6 + kx), acc);
            }
        }
        float vs = acc + __ldg(ob1 + ch);
        s_gb[ch * 4 + oo] = 0.5f * vs * (1.f + erff(vs * 0.70710678118654752f));

        const float4* ks_ = (const float4*)(g_wkT + g * 2048);
        const float4* vs_ = (const float4*)(g_wvT + g * 2048);
        float4* dw = (float4*)s_w;
        for (int idx = tid; idx < 512; idx += 256) {
            dw[idx]       = ks_[idx];
            dw[512 + idx] = vs_[idx];
        }
    }
    __syncthreads();

    // ---- P3: offsets ----
    {
        int w = tid >> 5, lane = tid & 31;
        int j = w & 3, comp = w >> 2;
        const float* o2 = ow2 + comp * 64;
        float acc = __ldg(o2 + lane) * s_gb[lane * 4 + j]
                  + __ldg(o2 + lane + 32) * s_gb[(lane + 32) * 4 + j];
        #pragma unroll
        for (int s = 16; s > 0; s >>= 1) acc += __shfl_xor_sync(0xffffffffu, acc, s);
        if (lane == 0) {
            float base = (comp == 0) ? (float)(j & 1) : (float)(j >> 1);
            float vg = base + 4.f * tanhf(acc);
            s_sp[comp * 4 + j]     = 8.f * vg - 0.5f;
            s_sp[8 + comp * 4 + j] = 2.f * vg - 1.f;
        }
    }
    __syncthreads();

    // ---- P4: bilinear sampling ----
    if (tid < 128) {
        int c = tid >> 2, j = tid & 3;
        float sx = s_sp[j], sy = s_sp[4 + j];
        float x0f = floorf(sx), y0f = floorf(sy);
        int x0 = (int)x0f, y0 = (int)y0f;
        float fx = sx - x0f, fy = sy - y0f;
        const float* xr = s_xg + c * 64;
        float acc = 0.f;
        if (y0 >= 0 && y0 < 8) {
            if (x0 >= 0 && x0 < 8)         acc = fmaf(xr[y0 * 8 + x0],       (1.f - fx) * (1.f - fy), acc);
            if (x0 + 1 >= 0 && x0 + 1 < 8) acc = fmaf(xr[y0 * 8 + x0 + 1],   fx * (1.f - fy),         acc);
        }
        if (y0 + 1 >= 0 && y0 + 1 < 8) {
            if (x0 >= 0 && x0 < 8)         acc = fmaf(xr[(y0 + 1) * 8 + x0],     (1.f - fx) * fy, acc);
            if (x0 + 1 >= 0 && x0 + 1 < 8) acc = fmaf(xr[(y0 + 1) * 8 + x0 + 1], fx * fy,         acc);
        }
        s_kv[c * 4 + j] = acc;
    }
    __syncthreads();

    // ---- P5: k, v projections (weights [c][o]: conflict-free broadcast reads) ----
    {
        int o = tid >> 2, j = tid & 3;
        float ak = 0.f, av = 0.f;
        const float* wkc = s_w + o;          // [c][o] stride 64
        const float* wvc = s_w + 2048 + o;
        #pragma unroll 8
        for (int c = 0; c < 32; c++) {
            float kvv = s_kv[c * 4 + j];
            ak = fmaf(wkc[c * 64], kvv, ak);
            av = fmaf(wvc[c * 64], kvv, av);
        }
        s_kkT[j * 68 + o] = ak;
        s_vvT[j * 68 + o] = av;
    }
    __syncthreads();

    // ---- P6a: sim via vectorized qT/kT reads, f32x2 packed accumulators ----
    float bx, by;
    {
        int i = tid >> 2, j = tid & 3;
        const float4* qv = (const float4*)(s_qT + i * 68);
        const float4* kv = (const float4*)(s_kkT + j * 68);
        float2 s01; s01.x = 0.f; s01.y = 0.f;
        float2 s23; s23.x = 0.f; s23.y = 0.f;
        #pragma unroll
        for (int t = 0; t < 16; t++) {
            float4 q4 = qv[t], k4 = kv[t];
            float2 qa; qa.x = q4.x; qa.y = q4.y;
            float2 qb; qb.x = q4.z; qb.y = q4.w;
            float2 ka; ka.x = k4.x; ka.y = k4.y;
            float2 kb; kb.x = k4.z; kb.y = k4.w;
            s01 = ffma2(qa, ka, s01);
            s23 = ffma2(qb, kb, s23);
        }
        s_lg[tid] = ((s01.x + s01.y) + (s23.x + s23.y)) * 0.125f;

        float qpx = (float)(i & 7) * (2.f / 7.f) - 1.f;
        float qpy = (float)(i >> 3) * (2.f / 7.f) - 1.f;
        float px = qpx - s_sp[8 + j];
        float py = qpy - s_sp[12 + j];
        bx = copysignf(log1pf(fabsf(px)), px);
        by = copysignf(log1pf(fabsf(py)), py);
    }
    __syncthreads();   // overlay region now free

    // ---- P6b: h1 (relu(cpb layer1)) via f32x2, bf16-packed STS.128; load w2b ----
    {
        char* base = (char*)sm + tid * 144;
        float2 bxp; bxp.x = bx; bxp.y = bx;
        float2 byp; byp.x = by; byp.y = by;
        #pragma unroll
        for (int u = 0; u < 8; u++) {
            float4 cx0 = *(const float4*)(s_c1 + u * 8);
            float4 cx1 = *(const float4*)(s_c1 + u * 8 + 4);
            float4 cy0 = *(const float4*)(s_c1 + 64 + u * 8);
            float4 cy1 = *(const float4*)(s_c1 + 64 + u * 8 + 4);
            float4 bb0 = *(const float4*)(s_b1 + u * 8);
            float4 bb1 = *(const float4*)(s_b1 + u * 8 + 4);
            float2 av[4];
            {
                float2 cxp, cyp, bbp;
                cxp.x = cx0.x; cxp.y = cx0.y; cyp.x = cy0.x; cyp.y = cy0.y;
                bbp.x = bb0.x; bbp.y = bb0.y;
                av[0] = ffma2(bxp, cxp, ffma2(byp, cyp, bbp));
                cxp.x = cx0.z; cxp.y = cx0.w; cyp.x = cy0.z; cyp.y = cy0.w;
                bbp.x = bb0.z; bbp.y = bb0.w;
                av[1] = ffma2(bxp, cxp, ffma2(byp, cyp, bbp));
                cxp.x = cx1.x; cxp.y = cx1.y; cyp.x = cy1.x; cyp.y = cy1.y;
                bbp.x = bb1.x; bbp.y = bb1.y;
                av[2] = ffma2(bxp, cxp, ffma2(byp, cyp, bbp));
                cxp.x = cx1.z; cxp.y = cx1.w; cyp.x = cy1.z; cyp.y = cy1.w;
                bbp.x = bb1.z; bbp.y = bb1.w;
                av[3] = ffma2(bxp, cxp, ffma2(byp, cyp, bbp));
            }
            unsigned hw[4];
            #pragma unroll
            for (int v = 0; v < 4; v++) {
                __nv_bfloat162 pr = __float22bfloat162_rn(
                    make_float2(fmaxf(av[v].x, 0.f), fmaxf(av[v].y, 0.f)));
                hw[v] = *(unsigned*)&pr;
            }
            uint4 pk; pk.x = hw[0]; pk.y = hw[1]; pk.z = hw[2]; pk.w = hw[3];
            *(uint4*)(base + 16 * u) = pk;
        }
        const uint4* w2s = (const uint4*)g_w2b;   // 64*72 bf16 = 576 uint4
        uint4* w2d = (uint4*)(sm + SM_W2B);
        for (int idx = tid; idx < 576; idx += 256) w2d[idx] = w2s[idx];
    }
    __syncthreads();

    // ---- P7: CPB layer2 bf16 MMA (144B strides, conflict-free fragment reads) ----
    {
        int wid = tid >> 5, lane = tid & 31;
        int p0 = wid * 32;
        const char* h1b = (const char*)sm;
        const char* w2b = (const char*)(sm + SM_W2B);
        float bias3 = s_b3[0];

        #pragma unroll
        for (int t = 0; t < 2; t++) {
            float d[8][4];
            #pragma unroll
            for (int nt = 0; nt < 8; nt++)
                #pragma unroll
                for (int r = 0; r < 4; r++) d[nt][r] = 0.f;

            #pragma unroll
            for (int ks = 0; ks < 4; ks++) {
                int cb = ks * 32 + 4 * (lane & 3);
                int row = p0 + t * 16 + (lane >> 2);
                unsigned a[4];
                a[0] = *(const unsigned*)(h1b + row * 144 + cb);
                a[1] = *(const unsigned*)(h1b + (row + 8) * 144 + cb);
                a[2] = *(const unsigned*)(h1b + row * 144 + cb + 16);
                a[3] = *(const unsigned*)(h1b + (row + 8) * 144 + cb + 16);
                #pragma unroll
                for (int nt = 0; nt < 8; nt++) {
                    int oo = nt * 8 + (lane >> 2);
                    unsigned b0 = *(const unsigned*)(w2b + oo * 144 + cb);
                    unsigned b1 = *(const unsigned*)(w2b + oo * 144 + cb + 16);
                    mma_bf16(d[nt], a, b0, b1);
                }
            }
            #pragma unroll
            for (int hf = 0; hf < 2; hf++) {
                float part = 0.f;
                #pragma unroll
                for (int nt = 0; nt < 8; nt++) {
                    int o0 = nt * 8 + 2 * (lane & 3);
                    float2 b2p = *(const float2*)(s_b2 + o0);
                    float2 c3p = *(const float2*)(s_c3 + o0);
                    float h2a = d[nt][hf * 2 + 0] + b2p.x;
                    float h2b = d[nt][hf * 2 + 1] + b2p.y;
                    part = fmaf(c3p.x, fmaxf(h2a, 0.f), part);
                    part = fmaf(c3p.y, fmaxf(h2b, 0.f), part);
                }
                part += __shfl_xor_sync(0xffffffffu, part, 1);
                part += __shfl_xor_sync(0xffffffffu, part, 2);
                if ((lane & 3) == 0) {
                    int p = p0 + t * 16 + hf * 8 + (lane >> 2);
                    s_lg[p] += part + bias3;
                }
            }
        }
    }
    __syncthreads();

    // ---- P9: per-thread softmax + out[i][d] -> g_ao [n][i][r], f32x2 packed ----
    {
        int i = tid >> 2, dg = tid & 3, d0 = dg * 16;
        float4 lg = *(const float4*)(s_lg + i * 4);
        float m = fmaxf(fmaxf(lg.x, lg.y), fmaxf(lg.z, lg.w));
        float e0 = expf(lg.x - m), e1 = expf(lg.y - m);
        float e2 = expf(lg.z - m), e3 = expf(lg.w - m);
        float inv = 1.f / (e0 + e1 + e2 + e3);
        float2 a0p, a1p, a2p, a3p;
        a0p.x = a0p.y = e0 * inv;
        a1p.x = a1p.y = e1 * inv;
        a2p.x = a2p.y = e2 * inv;
        a3p.x = a3p.y = e3 * inv;

        float* dst = g_ao + ((long)n * 64 + i) * 512 + g * 64 + d0;
        const float4* v0p = (const float4*)(s_vvT + 0 * 68 + d0);
        const float4* v1p = (const float4*)(s_vvT + 1 * 68 + d0);
        const float4* v2p = (const float4*)(s_vvT + 2 * 68 + d0);
        const float4* v3p = (const float4*)(s_vvT + 3 * 68 + d0);
        #pragma unroll
        for (int w = 0; w < 4; w++) {
            float4 v0 = v0p[w], v1 = v1p[w], v2 = v2p[w], v3 = v3p[w];
            float2 pa, pb, t;
            t.x = v0.x; t.y = v0.y; pa = fmul2(a0p, t);
            t.x = v1.x; t.y = v1.y; pa = ffma2(a1p, t, pa);
            t.x = v2.x; t.y = v2.y; pa = ffma2(a2p, t, pa);
            t.x = v3.x; t.y = v3.y; pa = ffma2(a3p, t, pa);
            t.x = v0.z; t.y = v0.w; pb = fmul2(a0p, t);
            t.x = v1.z; t.y = v1.w; pb = ffma2(a1p, t, pb);
            t.x = v2.z; t.y = v2.w; pb = ffma2(a2p, t, pb);
            t.x = v3.z; t.y = v3.w; pb = ffma2(a3p, t, pb);
            float4 o;
            o.x = cvt_tf32(pa.x); o.y = cvt_tf32(pa.y);
            o.z = cvt_tf32(pb.x); o.w = cvt_tf32(pb.y);
            *(float4*)(dst + w * 4) = o;
        }
    }
}

// ---------------- K3: output projection via tf32 MMA, cp.async double-buffered ----------------
#define K3_BUF_FLOATS (256 * 36 + 64 * 36)
#define K3_SMEM_BYTES (2 * K3_BUF_FLOATS * 4)
__global__ void __launch_bounds__(256) k3_outproj(const float* __restrict__ bo,
                                                  float* __restrict__ out) {
    extern __shared__ float sm3[];
    int n = blockIdx.x, tid = threadIdx.x;
    int wid = tid >> 5, lane = tid & 31;
    uint32_t sb_u32 = smem_u32(sm3);

    const float* wsrc = g_wo32;
    const float* asrc = g_ao + (long)n * 64 * 512;

    auto issue_slab = [&](int sl, int buf) {
        uint32_t base = sb_u32 + buf * (K3_BUF_FLOATS * 4);
        #pragma unroll
        for (int t = 0; t < 8; t++) {
            int idx = tid + t * 256;
            int c = idx >> 3, f = idx & 7;
            cpa16(base + (c * 36 + f * 4) * 4, wsrc + (long)c * 512 + sl * 32 + f * 4);
        }
        #pragma unroll
        for (int t = 0; t < 2; t++) {
            int idx = tid + t * 256;
            int i = idx >> 3, f = idx & 7;
            cpa16(base + (256 * 36 + i * 36 + f * 4) * 4, asrc + (long)i * 512 + sl * 32 + f * 4);
        }
    };

    float d[2][8][4];
    #pragma unroll
    for (int t = 0; t < 2; t++)
        #pragma unroll
        for (int nt = 0; nt < 8; nt++)
            #pragma unroll
            for (int r = 0; r < 4; r++) d[t][nt][r] = 0.f;

    issue_slab(0, 0);
    CPA_COMMIT();

    for (int s = 0; s < 16; s++) {
        if (s + 1 < 16) {
            issue_slab(s + 1, (s + 1) & 1);
            CPA_COMMIT();
            CPA_WAIT1();
        } else {
            CPA_WAIT0();
        }
        __syncthreads();

        const float* s_wb = sm3 + (s & 1) * K3_BUF_FLOATS;
        const float* s_ab = s_wb + 256 * 36;
        #pragma unroll
        for (int ks = 0; ks < 4; ks++) {
            int kk = ks * 8 + (lane & 3);
            unsigned a[2][4];
            #pragma unroll
            for (int t = 0; t < 2; t++) {
                int row = wid * 32 + t * 16 + (lane >> 2);
                a[t][0] = __float_as_uint(s_wb[row * 36 + kk]);
                a[t][1] = __float_as_uint(s_wb[(row + 8) * 36 + kk]);
                a[t][2] = __float_as_uint(s_wb[row * 36 + kk + 4]);
                a[t][3] = __float_as_uint(s_wb[(row + 8) * 36 + kk + 4]);
            }
            #pragma unroll
            for (int nt = 0; nt < 8; nt++) {
                int col = nt * 8 + (lane >> 2);
                unsigned b0 = __float_as_uint(s_ab[col * 36 + kk]);
                unsigned b1 = __float_as_uint(s_ab[col * 36 + kk + 4]);
                mma_tf32(d[0][nt], a[0], b0, b1);
                mma_tf32(d[1][nt], a[1], b0, b1);
            }
        }
        __syncthreads();
    }

    int it = n >> 7, jt = (n >> 4) & 7, b = n & 15;
    #pragma unroll
    for (int t = 0; t < 2; t++)
        #pragma unroll
        for (int hf = 0; hf < 2; hf++) {
            int c = wid * 32 + t * 16 + hf * 8 + (lane >> 2);
            float bias = __ldg(bo + c);
            #pragma unroll
            for (int nt = 0; nt < 8; nt++) {
                int i = nt * 8 + 2 * (lane & 3);
                int hh = it * 8 + (i >> 3), ww = jt * 8 + (i & 7);
                float2 v;
                v.x = d[t][nt][hf * 2 + 0] + bias;
                v.y = d[t][nt][hf * 2 + 1] + bias;
                *(float2*)(out + (((long)b * 256 + c) * 64 + hh) * 64 + ww) = v;
            }
        }
}

// ---------------- launcher ----------------
extern "C" void kernel_launch(void* const* d_in, const int* in_sizes, int n_in,
                              void* d_out, int out_size) {
    (void)in_sizes; (void)n_in; (void)out_size;
    const float* x   = (const float*)d_in[0];
    const float* lng = (const float*)d_in[1];
    const float* lnb = (const float*)d_in[2];
    const float* wq  = (const float*)d_in[3];
    const float* wk  = (const float*)d_in[4];
    const float* wv  = (const float*)d_in[5];
    const float* ow1 = (const float*)d_in[6];
    const float* ob1 = (const float*)d_in[7];
    const float* ow2 = (const float*)d_in[8];
    const float* cw1 = (const float*)d_in[9];
    const float* cb1 = (const float*)d_in[10];
    const float* cw2 = (const float*)d_in[11];
    const float* cb2 = (const float*)d_in[12];
    const float* cw3 = (const float*)d_in[13];
    const float* cb3 = (const float*)d_in[14];
    const float* wo  = (const float*)d_in[15];
    const float* bo  = (const float*)d_in[16];
    float* out = (float*)d_out;

    k1_ln_prep<<<2560, 256>>>(x, lng, lnb, wo, cw2, wq, wk, wv);
    cudaFuncSetAttribute(k2_attn, cudaFuncAttributeMaxDynamicSharedMemorySize, K2_SMEM_BYTES);
    k2_attn<<<NG, 256, K2_SMEM_BYTES>>>(ow1, ob1, ow2,
                                        cw1, cb1, cb2, cw3, cb3);
    cudaFuncSetAttribute(k3_outproj, cudaFuncAttributeMaxDynamicSharedMemorySize, K3_SMEM_BYTES);
    k3_outproj<<<NPATCH, 256, K3_SMEM_BYTES>>>(bo, out);
}